// round 4
// baseline (speedup 1.0000x reference)
#include <cuda_runtime.h>
#include <math.h>
#include <stdint.h>

// ---------------- problem constants ----------------
#define B_      1024
#define NTOK    54
#define WIN     49
#define NP      5
#define NH      12
#define HD      32
#define DIM     384
#define QKVD    1152
#define NWIN    64
#define WH      7
#define WW      7
#define SCALE   0.17677669529663687f
#define MTOK    (B_*NTOK)       // 55296
#define KDIM    384

// ---------------- scratch ----------------
__device__ float d_qkv[(size_t)MTOK * QKVD];
__device__ float d_att[(size_t)MTOK * DIM];
__device__ float d_bias[NH * NTOK * NTOK];

// ---------------- bias precompute ----------------
__global__ void bias_kernel(const float* __restrict__ rpb) {
    int idx = blockIdx.x * blockDim.x + threadIdx.x;
    const int total = NH * NTOK * NTOK;
    if (idx >= total) return;
    int h  = idx / (NTOK * NTOK);
    int r  = idx % (NTOK * NTOK);
    int qi = r / NTOK, kj = r % NTOK;
    float v = 0.f;
    if (qi >= NP && kj >= NP) {
        int i = qi - NP, j = kj - NP;
        int ih = i / WW, iw = i % WW;
        int jh = j / WW, jw = j % WW;
        int rpi = (ih - jh + WH - 1) * (2 * WW - 1) + (iw - jw + WW - 1);
        v = rpb[rpi * NH + h];
    }
    d_bias[idx] = v;
}

// ================= tf32 mma.sync GEMM, producer-converted =================
// C[M,N] = A[M,384] @ W[N,384]^T + bias ; M%128==0, N%128==0
#define BM 128
#define BN 128
#define BK 16
#define PAD_K 20

__device__ __forceinline__ uint32_t f2tf32(float f) {
    uint32_t r;
    asm("cvt.rna.tf32.f32 %0, %1;" : "=r"(r) : "f"(f));
    return r;
}

__device__ __forceinline__ void mma_tf32(float* c,
    uint32_t a0, uint32_t a1, uint32_t a2, uint32_t a3,
    uint32_t b0, uint32_t b1)
{
    asm volatile(
        "mma.sync.aligned.m16n8k8.row.col.f32.tf32.tf32.f32 "
        "{%0,%1,%2,%3}, {%4,%5,%6,%7}, {%8,%9}, {%0,%1,%2,%3};\n"
        : "+f"(c[0]), "+f"(c[1]), "+f"(c[2]), "+f"(c[3])
        : "r"(a0), "r"(a1), "r"(a2), "r"(a3), "r"(b0), "r"(b1));
}

__device__ __forceinline__ void sts_tf32x4(uint32_t* dst, float4 v) {
    dst[0] = f2tf32(v.x); dst[1] = f2tf32(v.y);
    dst[2] = f2tf32(v.z); dst[3] = f2tf32(v.w);
}

template<int N>
__device__ __forceinline__ void tgemm_body(
    const float* __restrict__ A, const float* __restrict__ W,
    const float* __restrict__ bias, float* __restrict__ C)
{
    __shared__ __align__(16) uint32_t As[2][BM * PAD_K];
    __shared__ __align__(16) uint32_t Bs[2][BN * PAD_K];

    const int tid  = threadIdx.x;
    const int warp = tid >> 5, lane = tid & 31;
    const int g    = lane >> 2, tg = lane & 3;
    const int wm   = warp & 1;
    const int wn   = warp >> 1;
    const int m0   = blockIdx.y * BM;
    const int n0   = blockIdx.x * BN;

    // producer: each thread owns (row lr, k-cols lk..lk+7) of both tiles
    const int lr = tid & 127;
    const int lk = (tid >> 7) * 8;            // 0 or 8
    const float* Ag = A + (size_t)(m0 + lr) * KDIM + lk;
    const float* Wg = W + (size_t)(n0 + lr) * KDIM + lk;
    const int soff = lr * PAD_K + lk;

    float acc[4][4][4];
    #pragma unroll
    for (int i = 0; i < 4; i++)
        #pragma unroll
        for (int j = 0; j < 4; j++)
            #pragma unroll
            for (int c = 0; c < 4; c++) acc[i][j][c] = 0.f;

    const int NT = KDIM / BK;                 // 24

    // prologue: stage tile 0
    float4 ar0 = *reinterpret_cast<const float4*>(Ag);
    float4 ar1 = *reinterpret_cast<const float4*>(Ag + 4);
    float4 wr0 = *reinterpret_cast<const float4*>(Wg);
    float4 wr1 = *reinterpret_cast<const float4*>(Wg + 4);

    for (int t = 0; t < NT; t++) {
        const int buf = t & 1;
        // store staged tile (converted) into smem
        sts_tf32x4(&As[buf][soff],     ar0);
        sts_tf32x4(&As[buf][soff + 4], ar1);
        sts_tf32x4(&Bs[buf][soff],     wr0);
        sts_tf32x4(&Bs[buf][soff + 4], wr1);
        __syncthreads();

        // prefetch next tile while MMAs run
        if (t + 1 < NT) {
            const float* ap = Ag + (t + 1) * BK;
            const float* wp = Wg + (t + 1) * BK;
            ar0 = *reinterpret_cast<const float4*>(ap);
            ar1 = *reinterpret_cast<const float4*>(ap + 4);
            wr0 = *reinterpret_cast<const float4*>(wp);
            wr1 = *reinterpret_cast<const float4*>(wp + 4);
        }

        const uint32_t* __restrict__ Asb = As[buf];
        const uint32_t* __restrict__ Bsb = Bs[buf];

        #pragma unroll
        for (int s = 0; s < 2; s++) {
            const int kb = s * 8;
            uint32_t af[4][4], bfr[4][2];
            #pragma unroll
            for (int i = 0; i < 4; i++) {
                const int rb = wm * 64 + i * 16;
                af[i][0] = Asb[(rb + g)     * PAD_K + kb + tg];
                af[i][1] = Asb[(rb + g + 8) * PAD_K + kb + tg];
                af[i][2] = Asb[(rb + g)     * PAD_K + kb + tg + 4];
                af[i][3] = Asb[(rb + g + 8) * PAD_K + kb + tg + 4];
            }
            #pragma unroll
            for (int j = 0; j < 4; j++) {
                const int cb = wn * 32 + j * 8;
                bfr[j][0] = Bsb[(cb + g) * PAD_K + kb + tg];
                bfr[j][1] = Bsb[(cb + g) * PAD_K + kb + tg + 4];
            }
            #pragma unroll
            for (int i = 0; i < 4; i++)
                #pragma unroll
                for (int j = 0; j < 4; j++)
                    mma_tf32(acc[i][j], af[i][0], af[i][1], af[i][2], af[i][3],
                             bfr[j][0], bfr[j][1]);
        }
        __syncthreads();
    }

    // epilogue: add bias, store
    #pragma unroll
    for (int i = 0; i < 4; i++) {
        const int rb = m0 + wm * 64 + i * 16 + g;
        #pragma unroll
        for (int j = 0; j < 4; j++) {
            const int cb = n0 + wn * 32 + j * 8 + 2 * tg;
            const float b0v = bias[cb], b1v = bias[cb + 1];
            float2 v0, v1;
            v0.x = acc[i][j][0] + b0v;  v0.y = acc[i][j][1] + b1v;
            v1.x = acc[i][j][2] + b0v;  v1.y = acc[i][j][3] + b1v;
            *reinterpret_cast<float2*>(&C[(size_t)rb * N + cb])       = v0;
            *reinterpret_cast<float2*>(&C[(size_t)(rb + 8) * N + cb]) = v1;
        }
    }
}

__global__ __launch_bounds__(256, 2) void k_qkv(
    const float* __restrict__ x, const float* __restrict__ W,
    const float* __restrict__ b)
{
    tgemm_body<QKVD>(x, W, b, d_qkv);
}

__global__ __launch_bounds__(256, 2) void k_proj(
    const float* __restrict__ W, const float* __restrict__ b,
    float* __restrict__ out)
{
    tgemm_body<DIM>(d_att, W, b, out);
}

// ================= fused attention: one block per (b, h) =================
__global__ __launch_bounds__(256) void attn_kernel(const float* __restrict__ mask)
{
    __shared__ float qs[64][32];         // q * SCALE (float2-friendly: stride 32)
    __shared__ float ks[64][34];         // stride 34 -> conflict-free LDS.64
    __shared__ float vs[64][33];
    __shared__ float2 ps2[8][64];        // packed probs for the row pair

    const int b = blockIdx.x / NH;
    const int h = blockIdx.x % NH;
    const int tid = threadIdx.x;

    const float* base = d_qkv + (size_t)b * NTOK * QKVD + h * HD;

    for (int idx = tid; idx < 64 * HD; idx += 256) {
        int r = idx >> 5, d = idx & 31;
        if (r < NTOK) {
            qs[r][d] = base[r * QKVD + d] * SCALE;
            ks[r][d] = base[r * QKVD + DIM + d];
            vs[r][d] = base[r * QKVD + 2 * DIM + d];
        } else {
            qs[r][d] = 0.f;
            ks[r][d] = 0.f;
            vs[r][d] = 0.f;
        }
    }
    __syncthreads();

    const int w    = tid >> 5;
    const int lane = tid & 31;
    const float* bptr = d_bias + h * NTOK * NTOK;
    const float* mptr = mask + (size_t)(b & (NWIN - 1)) * WIN * WIN;

    const int j0 = lane, j1 = lane + 32;
    const bool v1 = (j1 < NTOK);

    const float2* k0p = reinterpret_cast<const float2*>(&ks[j0][0]);
    const float2* k1p = reinterpret_cast<const float2*>(&ks[j1][0]);

    for (int r = w; r < NTOK; r += 16) {
        const bool has2 = (r + 8 < NTOK);
        const int r2 = has2 ? r + 8 : r;

        const float2* qap = reinterpret_cast<const float2*>(&qs[r][0]);
        const float2* qbp = reinterpret_cast<const float2*>(&qs[r2][0]);

        float s0 = 0.f, s1 = 0.f, u0 = 0.f, u1 = 0.f;
        #pragma unroll
        for (int d2 = 0; d2 < HD / 2; d2++) {
            const float2 k0 = k0p[d2];
            const float2 k1 = k1p[d2];
            const float2 qa = qap[d2];
            const float2 qb = qbp[d2];
            s0 += qa.x * k0.x + qa.y * k0.y;
            s1 += qa.x * k1.x + qa.y * k1.y;
            u0 += qb.x * k0.x + qb.y * k0.y;
            u1 += qb.x * k1.x + qb.y * k1.y;
        }
        s0 += bptr[r * NTOK + j0];
        u0 += bptr[r2 * NTOK + j0];
        s1 = v1 ? (s1 + bptr[r * NTOK + j1])  : -INFINITY;
        u1 = v1 ? (u1 + bptr[r2 * NTOK + j1]) : -INFINITY;
        if (j0 >= NP) {
            if (r  >= NP) s0 += mptr[(r  - NP) * WIN + (j0 - NP)];
            if (r2 >= NP) u0 += mptr[(r2 - NP) * WIN + (j0 - NP)];
        }
        if (v1) {
            if (r  >= NP) s1 += mptr[(r  - NP) * WIN + (j1 - NP)];
            if (r2 >= NP) u1 += mptr[(r2 - NP) * WIN + (j1 - NP)];
        }

        // softmax row r
        float mx = fmaxf(s0, s1);
        #pragma unroll
        for (int o = 16; o; o >>= 1) mx = fmaxf(mx, __shfl_xor_sync(0xffffffffu, mx, o));
        float e0 = __expf(s0 - mx);
        float e1 = v1 ? __expf(s1 - mx) : 0.f;
        float sm = e0 + e1;
        #pragma unroll
        for (int o = 16; o; o >>= 1) sm += __shfl_xor_sync(0xffffffffu, sm, o);
        float inv = 1.f / sm;

        // softmax row r2
        float mx2 = fmaxf(u0, u1);
        #pragma unroll
        for (int o = 16; o; o >>= 1) mx2 = fmaxf(mx2, __shfl_xor_sync(0xffffffffu, mx2, o));
        float f0 = __expf(u0 - mx2);
        float f1 = v1 ? __expf(u1 - mx2) : 0.f;
        float sm2 = f0 + f1;
        #pragma unroll
        for (int o = 16; o; o >>= 1) sm2 += __shfl_xor_sync(0xffffffffu, sm2, o);
        float inv2 = 1.f / sm2;

        ps2[w][j0] = make_float2(e0 * inv,  f0 * inv2);
        ps2[w][j1] = make_float2(e1 * inv,  f1 * inv2);
        __syncwarp();

        // PV: both rows share the vs loads
        float o0 = 0.f, o1 = 0.f;
        #pragma unroll
        for (int j = 0; j < NTOK; j++) {
            const float vj = vs[j][lane];
            const float2 p = ps2[w][j];
            o0 += p.x * vj;
            o1 += p.y * vj;
        }

        d_att[((size_t)b * NTOK + r) * DIM + h * HD + lane] = o0;
        if (has2)
            d_att[((size_t)b * NTOK + r2) * DIM + h * HD + lane] = o1;
        __syncwarp();
    }
}

// ---------------- launch ----------------
extern "C" void kernel_launch(void* const* d_in, const int* in_sizes, int n_in,
                              void* d_out, int out_size)
{
    const float* x      = (const float*)d_in[0];
    const float* mask   = (const float*)d_in[1];
    const float* qkv_w  = (const float*)d_in[2];
    const float* qkv_b  = (const float*)d_in[3];
    const float* proj_w = (const float*)d_in[4];
    const float* proj_b = (const float*)d_in[5];
    const float* rpb    = (const float*)d_in[6];
    float* out          = (float*)d_out;

    bias_kernel<<<(NH * NTOK * NTOK + 255) / 256, 256>>>(rpb);

    {   // QKV: (55296 x 384) @ (1152 x 384)^T
        dim3 grid(QKVD / BN, MTOK / BM);
        k_qkv<<<grid, 256>>>(x, qkv_w, qkv_b);
    }

    attn_kernel<<<B_ * NH, 256>>>(mask);

    {   // proj: (55296 x 384) @ (384 x 384)^T
        dim3 grid(DIM / BN, MTOK / BM);
        k_proj<<<grid, 256>>>(proj_w, proj_b, out);
    }
}

// round 5
// speedup vs baseline: 1.6025x; 1.6025x over previous
#include <cuda_runtime.h>
#include <math.h>
#include <stdint.h>

// ---------------- problem constants ----------------
#define B_      1024
#define NTOK    54
#define WIN     49
#define NP      5
#define NH      12
#define HD      32
#define DIM     384
#define QKVD    1152
#define NWIN    64
#define WH      7
#define WW      7
#define SCALE   0.17677669529663687f
#define MTOK    (B_*NTOK)       // 55296
#define KDIM    384

// ---------------- scratch ----------------
__device__ float d_qkv[(size_t)MTOK * QKVD];
__device__ float d_att[(size_t)MTOK * DIM];      // tf32-rounded attention output
__device__ float d_xr[(size_t)MTOK * DIM];       // tf32-rounded x
__device__ float d_wq[QKVD * DIM];               // tf32-rounded qkv_w
__device__ float d_wp[DIM * DIM];                // tf32-rounded proj_w
__device__ float d_bm[NH * NWIN * 64 * 64];      // combined bias+mask, padded

__device__ __forceinline__ uint32_t f2tf32(float f) {
    uint32_t r;
    asm("cvt.rna.tf32.f32 %0, %1;" : "=r"(r) : "f"(f));
    return r;
}

// ---------------- prepass: round arrays to tf32 ----------------
__global__ void round_tf32(const float* __restrict__ in, float* __restrict__ out, int n4) {
    int i = blockIdx.x * blockDim.x + threadIdx.x;
    if (i >= n4) return;
    float4 v = reinterpret_cast<const float4*>(in)[i];
    v.x = __uint_as_float(f2tf32(v.x));
    v.y = __uint_as_float(f2tf32(v.y));
    v.z = __uint_as_float(f2tf32(v.z));
    v.w = __uint_as_float(f2tf32(v.w));
    reinterpret_cast<float4*>(out)[i] = v;
}

// ---------------- prepass: combined bias+mask table ----------------
// d_bm[h][w][r][c], r,c in [0,64): bias(h,r,c)+mask(w,r,c) ; -1e30 for c>=54 (r<54); 0 for r>=54
__global__ void bm_kernel(const float* __restrict__ rpb, const float* __restrict__ mask) {
    int idx = blockIdx.x * blockDim.x + threadIdx.x;
    const int total = NH * NWIN * 64 * 64;
    if (idx >= total) return;
    int c  = idx & 63;
    int r  = (idx >> 6) & 63;
    int wv = (idx >> 12) & 63;
    int h  = idx >> 18;
    float v = 0.f;
    if (r < NTOK) {
        if (c < NTOK) {
            if (r >= NP && c >= NP) {
                int i = r - NP, j = c - NP;
                int ih = i / WW, iw = i % WW;
                int jh = j / WW, jw = j % WW;
                int rpi = (ih - jh + WH - 1) * (2 * WW - 1) + (iw - jw + WW - 1);
                v = rpb[rpi * NH + h] + mask[wv * WIN * WIN + i * WIN + j];
            }
        } else {
            v = -1e30f;
        }
    }
    d_bm[idx] = v;
}

// ================= tf32 mma.sync GEMM (R2 structure, no cvt in loop) =====
// C[M,N] = A[M,384] @ W[N,384]^T + bias ; inputs pre-rounded to tf32
#define BM 128
#define BN 128
#define BK 16
#define PAD_K 20
#define ABYTES (BM * PAD_K * 4)
#define BBYTES (BN * PAD_K * 4)

__device__ __forceinline__ void cp16(uint32_t smem, const float* g) {
    asm volatile("cp.async.cg.shared.global [%0], [%1], 16;\n" :: "r"(smem), "l"(g));
}

__device__ __forceinline__ void mma_tf32(float* c,
    uint32_t a0, uint32_t a1, uint32_t a2, uint32_t a3,
    uint32_t b0, uint32_t b1)
{
    asm volatile(
        "mma.sync.aligned.m16n8k8.row.col.f32.tf32.tf32.f32 "
        "{%0,%1,%2,%3}, {%4,%5,%6,%7}, {%8,%9}, {%0,%1,%2,%3};\n"
        : "+f"(c[0]), "+f"(c[1]), "+f"(c[2]), "+f"(c[3])
        : "r"(a0), "r"(a1), "r"(a2), "r"(a3), "r"(b0), "r"(b1));
}

template<int N>
__device__ __forceinline__ void tgemm_body(
    const float* __restrict__ A, const float* __restrict__ W,
    const float* __restrict__ bias, float* __restrict__ C, int K)
{
    __shared__ __align__(16) float As[2][BM * PAD_K];
    __shared__ __align__(16) float Bs[2][BN * PAD_K];

    const int tid  = threadIdx.x;
    const int warp = tid >> 5, lane = tid & 31;
    const int g    = lane >> 2, tg = lane & 3;
    const int wm   = warp & 1;
    const int wn   = warp >> 1;
    const int m0   = blockIdx.y * BM;
    const int n0   = blockIdx.x * BN;

    const int lr = tid >> 2;
    const int lk = (tid & 3) * 4;
    const float* Ag = A + (size_t)(m0 + lr) * K + lk;
    const float* Wg = W + (size_t)(n0 + lr) * K + lk;

    uint32_t sA = (uint32_t)__cvta_generic_to_shared(&As[0][0]);
    uint32_t sB = (uint32_t)__cvta_generic_to_shared(&Bs[0][0]);
    const uint32_t sA0 = sA + (lr * PAD_K + lk) * 4;
    const uint32_t sA1 = sA + ((lr + 64) * PAD_K + lk) * 4;
    const uint32_t sB0 = sB + (lr * PAD_K + lk) * 4;
    const uint32_t sB1 = sB + ((lr + 64) * PAD_K + lk) * 4;

    float acc[4][4][4];
    #pragma unroll
    for (int i = 0; i < 4; i++)
        #pragma unroll
        for (int j = 0; j < 4; j++)
            #pragma unroll
            for (int c = 0; c < 4; c++) acc[i][j][c] = 0.f;

    const int nt = K / BK;

    {
        cp16(sA0, Ag);  cp16(sA1, Ag + (size_t)64 * K);
        cp16(sB0, Wg);  cp16(sB1, Wg + (size_t)64 * K);
        asm volatile("cp.async.commit_group;\n");
    }

    for (int t = 0; t < nt; t++) {
        asm volatile("cp.async.wait_group 0;\n");
        __syncthreads();
        const int buf = t & 1;
        if (t + 1 < nt) {
            const float* ap = Ag + (size_t)(t + 1) * BK;
            const float* wp = Wg + (size_t)(t + 1) * BK;
            const uint32_t bo = (buf ^ 1) ? 1u : 0u;
            cp16(sA0 + bo * ABYTES, ap);
            cp16(sA1 + bo * ABYTES, ap + (size_t)64 * K);
            cp16(sB0 + bo * BBYTES, wp);
            cp16(sB1 + bo * BBYTES, wp + (size_t)64 * K);
            asm volatile("cp.async.commit_group;\n");
        }

        const float* __restrict__ Asb = As[buf];
        const float* __restrict__ Bsb = Bs[buf];

        #pragma unroll
        for (int s = 0; s < 2; s++) {
            const int kb = s * 8;
            uint32_t af[4][4], bfr[4][2];
            #pragma unroll
            for (int i = 0; i < 4; i++) {
                const int rb = wm * 64 + i * 16;
                af[i][0] = __float_as_uint(Asb[(rb + g)     * PAD_K + kb + tg]);
                af[i][1] = __float_as_uint(Asb[(rb + g + 8) * PAD_K + kb + tg]);
                af[i][2] = __float_as_uint(Asb[(rb + g)     * PAD_K + kb + tg + 4]);
                af[i][3] = __float_as_uint(Asb[(rb + g + 8) * PAD_K + kb + tg + 4]);
            }
            #pragma unroll
            for (int j = 0; j < 4; j++) {
                const int cb = wn * 32 + j * 8;
                bfr[j][0] = __float_as_uint(Bsb[(cb + g) * PAD_K + kb + tg]);
                bfr[j][1] = __float_as_uint(Bsb[(cb + g) * PAD_K + kb + tg + 4]);
            }
            #pragma unroll
            for (int i = 0; i < 4; i++)
                #pragma unroll
                for (int j = 0; j < 4; j++)
                    mma_tf32(acc[i][j], af[i][0], af[i][1], af[i][2], af[i][3],
                             bfr[j][0], bfr[j][1]);
        }
        __syncthreads();
    }

    #pragma unroll
    for (int i = 0; i < 4; i++) {
        const int rb = m0 + wm * 64 + i * 16 + g;
        #pragma unroll
        for (int j = 0; j < 4; j++) {
            const int cb = n0 + wn * 32 + j * 8 + 2 * tg;
            const float b0v = bias[cb], b1v = bias[cb + 1];
            float2 v0, v1;
            v0.x = acc[i][j][0] + b0v;  v0.y = acc[i][j][1] + b1v;
            v1.x = acc[i][j][2] + b0v;  v1.y = acc[i][j][3] + b1v;
            *reinterpret_cast<float2*>(&C[(size_t)rb * N + cb])       = v0;
            *reinterpret_cast<float2*>(&C[(size_t)(rb + 8) * N + cb]) = v1;
        }
    }
}

__global__ __launch_bounds__(256, 2) void k_qkv(const float* __restrict__ b)
{
    tgemm_body<QKVD>(d_xr, d_wq, b, d_qkv, KDIM);
}

__global__ __launch_bounds__(256, 2) void k_proj(const float* __restrict__ b,
                                                 float* __restrict__ out)
{
    tgemm_body<DIM>(d_att, d_wp, b, out, KDIM);
}

// ================= tensor-core attention: one block (128 thr) per (b,h) ==
// smem layout (uint32 units):
//   QH  [64][36]  @ 0      (2304)
//   KH  [64][36]  @ 2304   (2304)
//   VT  [32][68]  @ 4608   (2176)   V transposed [hd][key]
//   U   @ 6784:  QL [64][36] (2304) + KL [64][36] (2304)   -- during QK
//                PP [64][68] (4352)                         -- after QK
// total 11392 u32 = 45568 B  (< 48KB static)
#define SQH 0
#define SKH 2304
#define SVT 4608
#define SQL 6784
#define SKL (6784 + 2304)
#define SPP 6784
#define SMTOT 11392

__global__ __launch_bounds__(128) void attn_tc()
{
    __shared__ uint32_t sm[SMTOT];

    const int b = blockIdx.x / NH;
    const int h = blockIdx.x % NH;
    const int tid = threadIdx.x;

    const float* base = d_qkv + (size_t)b * NTOK * QKVD + h * HD;

    // load & convert
    for (int idx = tid; idx < 64 * 32; idx += 128) {
        const int r = idx >> 5, d = idx & 31;
        float qv = 0.f, kv = 0.f, vv = 0.f;
        if (r < NTOK) {
            qv = base[r * QKVD + d] * SCALE;
            kv = base[r * QKVD + DIM + d];
            vv = base[r * QKVD + 2 * DIM + d];
        }
        const uint32_t qhi = f2tf32(qv);
        const uint32_t khi = f2tf32(kv);
        const float qlo = qv - __uint_as_float(qhi);
        const float klo = kv - __uint_as_float(khi);
        sm[SQH + r * 36 + d] = qhi;
        sm[SKH + r * 36 + d] = khi;
        sm[SQL + r * 36 + d] = f2tf32(qlo);
        sm[SKL + r * 36 + d] = f2tf32(klo);
        sm[SVT + d * 68 + r] = f2tf32(vv);
    }
    __syncthreads();

    const int w = tid >> 5, lane = tid & 31;
    const int g = lane >> 2, tg = lane & 3;
    const int r0 = w * 16 + g;          // rows r0 and r0+8

    // ---- QK^T with hi/lo split (3 MMAs) ----
    float s[8][4];
    #pragma unroll
    for (int j = 0; j < 8; j++)
        #pragma unroll
        for (int c = 0; c < 4; c++) s[j][c] = 0.f;

    #pragma unroll
    for (int kk = 0; kk < 4; kk++) {
        const int ko = kk * 8;
        const uint32_t a0 = sm[SQH + r0 * 36 + ko + tg];
        const uint32_t a1 = sm[SQH + (r0 + 8) * 36 + ko + tg];
        const uint32_t a2 = sm[SQH + r0 * 36 + ko + tg + 4];
        const uint32_t a3 = sm[SQH + (r0 + 8) * 36 + ko + tg + 4];
        const uint32_t l0 = sm[SQL + r0 * 36 + ko + tg];
        const uint32_t l1 = sm[SQL + (r0 + 8) * 36 + ko + tg];
        const uint32_t l2 = sm[SQL + r0 * 36 + ko + tg + 4];
        const uint32_t l3 = sm[SQL + (r0 + 8) * 36 + ko + tg + 4];
        #pragma unroll
        for (int j = 0; j < 8; j++) {
            const int kr = j * 8 + g;
            const uint32_t b0 = sm[SKH + kr * 36 + ko + tg];
            const uint32_t b1 = sm[SKH + kr * 36 + ko + tg + 4];
            const uint32_t c0 = sm[SKL + kr * 36 + ko + tg];
            const uint32_t c1 = sm[SKL + kr * 36 + ko + tg + 4];
            mma_tf32(s[j], a0, a1, a2, a3, b0, b1);
            mma_tf32(s[j], l0, l1, l2, l3, b0, b1);
            mma_tf32(s[j], a0, a1, a2, a3, c0, c1);
        }
    }

    // ---- bias+mask add (from precomputed d_bm, L2-resident) ----
    const float* bmp = d_bm + ((size_t)(h * NWIN + (b & (NWIN - 1)))) * 64 * 64;
    #pragma unroll
    for (int j = 0; j < 8; j++) {
        const float2 t0 = *reinterpret_cast<const float2*>(&bmp[r0 * 64 + j * 8 + 2 * tg]);
        const float2 t1 = *reinterpret_cast<const float2*>(&bmp[(r0 + 8) * 64 + j * 8 + 2 * tg]);
        s[j][0] += t0.x;  s[j][1] += t0.y;
        s[j][2] += t1.x;  s[j][3] += t1.y;
    }

    // ---- softmax (rows r0 via c0/c1, r0+8 via c2/c3) ----
    float m0 = -1e30f, m1 = -1e30f;
    #pragma unroll
    for (int j = 0; j < 8; j++) {
        m0 = fmaxf(m0, fmaxf(s[j][0], s[j][1]));
        m1 = fmaxf(m1, fmaxf(s[j][2], s[j][3]));
    }
    m0 = fmaxf(m0, __shfl_xor_sync(0xffffffffu, m0, 1));
    m0 = fmaxf(m0, __shfl_xor_sync(0xffffffffu, m0, 2));
    m1 = fmaxf(m1, __shfl_xor_sync(0xffffffffu, m1, 1));
    m1 = fmaxf(m1, __shfl_xor_sync(0xffffffffu, m1, 2));

    float sum0 = 0.f, sum1 = 0.f;
    #pragma unroll
    for (int j = 0; j < 8; j++) {
        s[j][0] = __expf(s[j][0] - m0);
        s[j][1] = __expf(s[j][1] - m0);
        s[j][2] = __expf(s[j][2] - m1);
        s[j][3] = __expf(s[j][3] - m1);
        sum0 += s[j][0] + s[j][1];
        sum1 += s[j][2] + s[j][3];
    }
    sum0 += __shfl_xor_sync(0xffffffffu, sum0, 1);
    sum0 += __shfl_xor_sync(0xffffffffu, sum0, 2);
    sum1 += __shfl_xor_sync(0xffffffffu, sum1, 1);
    sum1 += __shfl_xor_sync(0xffffffffu, sum1, 2);
    const float inv0 = 1.f / sum0;
    const float inv1 = 1.f / sum1;

    // all warps must be done reading QL/KL before PP overwrites that region
    __syncthreads();

    // ---- write P (tf32) ----
    #pragma unroll
    for (int j = 0; j < 8; j++) {
        uint2 p0, p1;
        p0.x = f2tf32(s[j][0] * inv0);  p0.y = f2tf32(s[j][1] * inv0);
        p1.x = f2tf32(s[j][2] * inv1);  p1.y = f2tf32(s[j][3] * inv1);
        *reinterpret_cast<uint2*>(&sm[SPP + r0 * 68 + j * 8 + 2 * tg])       = p0;
        *reinterpret_cast<uint2*>(&sm[SPP + (r0 + 8) * 68 + j * 8 + 2 * tg]) = p1;
    }
    __syncwarp();

    // ---- PV ----
    float o[4][4];
    #pragma unroll
    for (int n = 0; n < 4; n++)
        #pragma unroll
        for (int c = 0; c < 4; c++) o[n][c] = 0.f;

    #pragma unroll
    for (int kk = 0; kk < 8; kk++) {
        const int ko = kk * 8;
        const uint32_t a0 = sm[SPP + r0 * 68 + ko + tg];
        const uint32_t a1 = sm[SPP + (r0 + 8) * 68 + ko + tg];
        const uint32_t a2 = sm[SPP + r0 * 68 + ko + tg + 4];
        const uint32_t a3 = sm[SPP + (r0 + 8) * 68 + ko + tg + 4];
        #pragma unroll
        for (int n = 0; n < 4; n++) {
            const int vr = n * 8 + g;
            const uint32_t b0 = sm[SVT + vr * 68 + ko + tg];
            const uint32_t b1 = sm[SVT + vr * 68 + ko + tg + 4];
            mma_tf32(o[n], a0, a1, a2, a3, b0, b1);
        }
    }

    // ---- store (tf32-rounded for the proj GEMM) ----
    if (r0 < NTOK) {
        float* op = d_att + ((size_t)b * NTOK + r0) * DIM + h * HD;
        #pragma unroll
        for (int n = 0; n < 4; n++) {
            float2 v;
            v.x = __uint_as_float(f2tf32(o[n][0]));
            v.y = __uint_as_float(f2tf32(o[n][1]));
            *reinterpret_cast<float2*>(&op[n * 8 + 2 * tg]) = v;
        }
    }
    if (r0 + 8 < NTOK) {
        float* op = d_att + ((size_t)b * NTOK + r0 + 8) * DIM + h * HD;
        #pragma unroll
        for (int n = 0; n < 4; n++) {
            float2 v;
            v.x = __uint_as_float(f2tf32(o[n][2]));
            v.y = __uint_as_float(f2tf32(o[n][3]));
            *reinterpret_cast<float2*>(&op[n * 8 + 2 * tg]) = v;
        }
    }
}

// ---------------- launch ----------------
extern "C" void kernel_launch(void* const* d_in, const int* in_sizes, int n_in,
                              void* d_out, int out_size)
{
    const float* x      = (const float*)d_in[0];
    const float* mask   = (const float*)d_in[1];
    const float* qkv_w  = (const float*)d_in[2];
    const float* qkv_b  = (const float*)d_in[3];
    const float* proj_w = (const float*)d_in[4];
    const float* proj_b = (const float*)d_in[5];
    const float* rpb    = (const float*)d_in[6];
    float* out          = (float*)d_out;

    float *xr, *wq, *wp;
    cudaGetSymbolAddress((void**)&xr, d_xr);
    cudaGetSymbolAddress((void**)&wq, d_wq);
    cudaGetSymbolAddress((void**)&wp, d_wp);

    // prepasses
    {
        int n4 = (MTOK * DIM) / 4;
        round_tf32<<<(n4 + 255) / 256, 256>>>(x, xr, n4);
        n4 = (QKVD * DIM) / 4;
        round_tf32<<<(n4 + 255) / 256, 256>>>(qkv_w, wq, n4);
        n4 = (DIM * DIM) / 4;
        round_tf32<<<(n4 + 255) / 256, 256>>>(proj_w, wp, n4);
        const int total = NH * NWIN * 64 * 64;
        bm_kernel<<<(total + 255) / 256, 256>>>(rpb, mask);
    }

    {   // QKV: (55296 x 384) @ (1152 x 384)^T
        dim3 grid(QKVD / BN, MTOK / BM);
        k_qkv<<<grid, 256>>>(qkv_b);
    }

    attn_tc<<<B_ * NH, 128>>>();

    {   // proj: (55296 x 384) @ (384 x 384)^T
        dim3 grid(DIM / BN, MTOK / BM);
        k_proj<<<grid, 256>>>(proj_b, out);
    }
}